// round 16
// baseline (speedup 1.0000x reference)
#include <cuda_runtime.h>
#include <math_constants.h>

// CRF Viterbi decode: two kernels (emit GEMM + scan), software-pipelined
// across TWO streams with fork-join events so scan(g) overlaps emit(g+1).
//   X: [4096, 512, 128] f32   W: [26, 128] f32   T: [26, 26] f32
//   out: [4096, 512] labels as FLOAT32 values (0.0 .. 25.0).
// Numerics bit-identical to R15 (canary rel_err 6.390682e-4).

#define LSEQ   512
#define KLAB   26
#define DDIM   128
#define WPITCH 132
#define EPITCH 28          // e_buf row pitch floats (112 B, 16B-aligned)
#define BATCH  4096
#define WPB    2           // words per CTA in scan kernel
#define NGRP   8           // pipeline groups
#define GRPW   (BATCH / NGRP)   // 512 words per group

typedef unsigned long long u64;
union F2 { u64 u; float2 f; };

__device__ __forceinline__ F2 add2(F2 a, F2 b) {
    F2 r;
    asm("add.rn.f32x2 %0, %1, %2;" : "=l"(r.u) : "l"(a.u), "l"(b.u));
    return r;
}
__device__ __forceinline__ void fma2(u64& d, u64 a, u64 b) {
    asm("fma.rn.f32x2 %0, %1, %2, %0;" : "+l"(d) : "l"(a), "l"(b));
}
__device__ __forceinline__ float lo_f(u64 v) { F2 t; t.u = v; return t.f.x; }
__device__ __forceinline__ float hi_f(u64 v) { F2 t; t.u = v; return t.f.y; }

// Scratch: emissions, 4096 * 512 * 28 floats = 224 MiB (device global).
__device__ float e_buf[(size_t)BATCH * LSEQ * EPITCH];

// ============================ Kernel A: GEMM ============================
// Processes words [word0, word0 + GRPW).
__global__ __launch_bounds__(128) void crf_emit_kernel(
    const float* __restrict__ X,
    const float* __restrict__ W,
    int word0)
{
    __shared__ __align__(16) float w_sm[KLAB * WPITCH];   // 13728 B
    __shared__ __align__(16) float x_sm[4][8 * DDIM];     // 16384 B

    const int b    = word0 + blockIdx.x;
    const int tid  = threadIdx.x;
    const int warp = tid >> 5;
    const int lane = tid & 31;

    for (int idx = tid; idx < KLAB * DDIM; idx += blockDim.x) {
        int k = idx >> 7;
        int d = idx & 127;
        w_sm[k * WPITCH + d] = W[idx];
    }
    __syncthreads();

    const int kk = lane < KLAB ? lane : 0;
    const ulonglong2* w2 = reinterpret_cast<const ulonglong2*>(w_sm + kk * WPITCH);
    float* xs = x_sm[warp];
    const ulonglong2* xs2 = reinterpret_cast<const ulonglong2*>(xs);

    const int wrow0 = warp * 128;
    for (int blk = 0; blk < 16; blk++) {
        const int row0 = wrow0 + blk * 8;

        #pragma unroll
        for (int k = 0; k < 8; k++)
            reinterpret_cast<float4*>(xs + k * DDIM)[lane] =
                reinterpret_cast<const float4*>(
                    X + ((size_t)b * LSEQ + row0 + k) * DDIM)[lane];
        __syncwarp();

        u64 aL[8], aH[8];
        #pragma unroll
        for (int k = 0; k < 8; k++) { aL[k] = 0ull; aH[k] = 0ull; }

        #pragma unroll 4
        for (int q = 0; q < DDIM / 4; q++) {
            const ulonglong2 wv = w2[q];
            #pragma unroll
            for (int k = 0; k < 8; k++) {
                const ulonglong2 xv = xs2[k * (DDIM / 4) + q];
                fma2(aL[k], xv.x, wv.x);   // k%4 == 0,1 partials
                fma2(aH[k], xv.y, wv.y);   // k%4 == 2,3 partials
            }
        }
        if (lane < KLAB) {
            #pragma unroll
            for (int k = 0; k < 8; k++) {
                const float e = (lo_f(aL[k]) + hi_f(aL[k]))
                              + (lo_f(aH[k]) + hi_f(aH[k]));
                e_buf[((size_t)b * LSEQ + row0 + k) * EPITCH + lane] = e;
            }
        }
        __syncwarp();
    }
}

// ============================ Kernel B: scan ============================
__global__ __launch_bounds__(64) void crf_scan_kernel(
    const float* __restrict__ T,
    float* __restrict__ out,
    int word0)
{
    __shared__ unsigned char bp_sm[WPB][(LSEQ - 1) * KLAB]; // 2 x 13286 B
    __shared__ __align__(16) float l_sm[WPB][32];
    __shared__ unsigned char lab[WPB][LSEQ];

    const int warp = threadIdx.x >> 5;     // 0..1 = word slot
    const int lane = threadIdx.x & 31;
    const int word = word0 + blockIdx.x * WPB + warp;
    const int yy   = lane < KLAB ? lane : 0;

    F2 T2[13];
    #pragma unroll
    for (int h = 0; h < 13; h++) {
        T2[h].f.x = T[(2 * h)     * KLAB + yy];
        T2[h].f.y = T[(2 * h + 1) * KLAB + yy];
    }

    l_sm[warp][lane] = 0.0f;
    __syncwarp();

    const float* erow = e_buf + (size_t)word * LSEQ * EPITCH;
    const ulonglong2* lr2 = reinterpret_cast<const ulonglong2*>(l_sm[warp]);

    ulonglong2 ev[7];
    {
        const ulonglong2* r0 = reinterpret_cast<const ulonglong2*>(erow);
        #pragma unroll
        for (int h = 0; h < 7; h++) ev[h] = r0[h];
    }

    float lcur = 0.0f;
    for (int t = 0; t < LSEQ - 1; t++) {
        ulonglong2 nv[7];
        {
            const ulonglong2* rn = reinterpret_cast<const ulonglong2*>(
                erow + (size_t)(t + 1) * EPITCH);
            #pragma unroll
            for (int h = 0; h < 7; h++) nv[h] = rn[h];
            const int pt = (t + 16 < LSEQ) ? t + 16 : LSEQ - 1;
            asm volatile("prefetch.global.L2 [%0];"
                         :: "l"(erow + (size_t)pt * EPITCH));
        }

        // s_j = (e_j + T_jy) + l_j, packed pairs (exact association).
        F2 sv[13];
        #pragma unroll
        for (int h4 = 0; h4 < 7; h4++) {
            const ulonglong2 l4 = lr2[h4];
            F2 ea, la, u;
            ea.u = ev[h4].x; la.u = l4.x;
            u = add2(ea, T2[2 * h4]);
            sv[2 * h4] = add2(u, la);
            if (2 * h4 + 1 < 13) {
                F2 ob, lb;
                ob.u = ev[h4].y; lb.u = l4.y;
                u = add2(ob, T2[2 * h4 + 1]);
                sv[2 * h4 + 1] = add2(u, lb);
            }
        }

        // Exact max via fmaxf tree.
        float t13[13];
        #pragma unroll
        for (int h = 0; h < 13; h++) t13[h] = fmaxf(sv[h].f.x, sv[h].f.y);
        float r7[7];
        #pragma unroll
        for (int h = 0; h < 6; h++) r7[h] = fmaxf(t13[2 * h], t13[2 * h + 1]);
        r7[6] = t13[12];
        float r4[4];
        r4[0] = fmaxf(r7[0], r7[1]);
        r4[1] = fmaxf(r7[2], r7[3]);
        r4[2] = fmaxf(r7[4], r7[5]);
        r4[3] = r7[6];
        const float m = fmaxf(fmaxf(r4[0], r4[1]), fmaxf(r4[2], r4[3]));

        // First-occurrence argmax: descending eq-chain.
        int am = 25;
        #pragma unroll
        for (int j = 24; j >= 0; j--) {
            const float sj = (j & 1) ? sv[j >> 1].f.y : sv[j >> 1].f.x;
            if (sj == m) am = j;
        }

        if (lane < KLAB) {
            bp_sm[warp][t * KLAB + lane] = (unsigned char)am;
            l_sm[warp][lane] = m;
        }
        lcur = m;

        #pragma unroll
        for (int h = 0; h < 7; h++) ev[h] = nv[h];
        __syncwarp();
    }

    float fs = (lane < KLAB)
                   ? (erow[(size_t)(LSEQ - 1) * EPITCH + yy] + lcur)
                   : -CUDART_INF_F;
    int idx = lane;
    #pragma unroll
    for (int off = 16; off > 0; off >>= 1) {
        float ov = __shfl_down_sync(0xffffffffu, fs, off);
        int   oi = __shfl_down_sync(0xffffffffu, idx, off);
        if (ov > fs || (ov == fs && oi < idx)) { fs = ov; idx = oi; }
    }
    int y_last = __shfl_sync(0xffffffffu, idx, 0);

    if (lane == 0) {
        int yv = y_last;
        lab[warp][LSEQ - 1] = (unsigned char)yv;
        for (int t = LSEQ - 2; t >= 0; t--) {
            yv = bp_sm[warp][t * KLAB + yv];
            lab[warp][t] = (unsigned char)yv;
        }
    }
    __syncwarp();

    float* orow = out + (size_t)word * LSEQ;
    for (int i = lane; i < LSEQ; i += 32)
        orow[i] = (float)lab[warp][i];
}

extern "C" void kernel_launch(void* const* d_in, const int* in_sizes, int n_in,
                              void* d_out, int out_size)
{
    int ix = 0, it = 0;
    for (int i = 1; i < n_in && i < 3; i++) {
        if (in_sizes[i] > in_sizes[ix]) ix = i;
        if (in_sizes[i] < in_sizes[it]) it = i;
    }
    int iw = 3 - ix - it;
    if (n_in < 3 || iw < 0 || iw > 2 || ix == it) { ix = 0; iw = 1; it = 2; }

    const float* X = (const float*)d_in[ix];
    const float* W = (const float*)d_in[iw];
    const float* T = (const float*)d_in[it];
    float* out = (float*)d_out;
    (void)out_size;

    // Two-stream fork-join pipeline: emit(g) on s0; scan(g) on s1 after
    // emit(g)'s event; scan(g) overlaps emit(g+1). Graph-capture-legal
    // (event-based fork from and join to the launch stream). Host-side
    // stream/event creation only (no device memory).
    cudaStream_t s1;
    cudaStreamCreateWithFlags(&s1, cudaStreamNonBlocking);
    cudaEvent_t evFork, evJoin, evE[NGRP];
    cudaEventCreateWithFlags(&evFork, cudaEventDisableTiming);
    cudaEventCreateWithFlags(&evJoin, cudaEventDisableTiming);
    for (int g = 0; g < NGRP; g++)
        cudaEventCreateWithFlags(&evE[g], cudaEventDisableTiming);

    // Fork: s1 joins the (possibly capturing) origin stream's graph.
    cudaEventRecord(evFork, 0);
    cudaStreamWaitEvent(s1, evFork, 0);

    for (int g = 0; g < NGRP; g++) {
        const int w0 = g * GRPW;
        crf_emit_kernel<<<GRPW, 128, 0, 0>>>(X, W, w0);
        cudaEventRecord(evE[g], 0);
        cudaStreamWaitEvent(s1, evE[g], 0);
        crf_scan_kernel<<<GRPW / WPB, 32 * WPB, 0, s1>>>(T, out, w0);
    }

    // Join: origin stream waits for all scans before returning.
    cudaEventRecord(evJoin, s1);
    cudaStreamWaitEvent(0, evJoin, 0);
}

// round 17
// speedup vs baseline: 1.7071x; 1.7071x over previous
#include <cuda_runtime.h>
#include <math_constants.h>

// CRF Viterbi decode: emit GEMM + scan kernels, 2-group two-stream pipeline.
//   X: [4096, 512, 128] f32   W: [26, 128] f32   T: [26, 26] f32
//   out: [4096, 512] labels as FLOAT32 values (0.0 .. 25.0).
// R17: scan gets a 32-row smem ring with 16-step-deep coalesced prefetch
// (e loads off the critical path); pipeline groups 8 -> 2.
// Numerics bit-identical (canary rel_err 6.390682e-4).

#define LSEQ   512
#define KLAB   26
#define DDIM   128
#define WPITCH 132
#define EPITCH 28          // e_buf row pitch floats (112 B, 16B-aligned)
#define BATCH  4096
#define WPB    2           // words per CTA in scan kernel
#define NGRP   2           // pipeline groups
#define GRPW   (BATCH / NGRP)   // 2048 words per group

typedef unsigned long long u64;
union F2 { u64 u; float2 f; };

__device__ __forceinline__ F2 add2(F2 a, F2 b) {
    F2 r;
    asm("add.rn.f32x2 %0, %1, %2;" : "=l"(r.u) : "l"(a.u), "l"(b.u));
    return r;
}
__device__ __forceinline__ void fma2(u64& d, u64 a, u64 b) {
    asm("fma.rn.f32x2 %0, %1, %2, %0;" : "+l"(d) : "l"(a), "l"(b));
}
__device__ __forceinline__ float lo_f(u64 v) { F2 t; t.u = v; return t.f.x; }
__device__ __forceinline__ float hi_f(u64 v) { F2 t; t.u = v; return t.f.y; }

// Scratch: emissions, 4096 * 512 * 28 floats = 224 MiB (device global).
__device__ float e_buf[(size_t)BATCH * LSEQ * EPITCH];

// ============================ Kernel A: GEMM ============================
__global__ __launch_bounds__(128) void crf_emit_kernel(
    const float* __restrict__ X,
    const float* __restrict__ W,
    int word0)
{
    __shared__ __align__(16) float w_sm[KLAB * WPITCH];   // 13728 B
    __shared__ __align__(16) float x_sm[4][8 * DDIM];     // 16384 B

    const int b    = word0 + blockIdx.x;
    const int tid  = threadIdx.x;
    const int warp = tid >> 5;
    const int lane = tid & 31;

    for (int idx = tid; idx < KLAB * DDIM; idx += blockDim.x) {
        int k = idx >> 7;
        int d = idx & 127;
        w_sm[k * WPITCH + d] = W[idx];
    }
    __syncthreads();

    const int kk = lane < KLAB ? lane : 0;
    const ulonglong2* w2 = reinterpret_cast<const ulonglong2*>(w_sm + kk * WPITCH);
    float* xs = x_sm[warp];
    const ulonglong2* xs2 = reinterpret_cast<const ulonglong2*>(xs);

    const int wrow0 = warp * 128;
    for (int blk = 0; blk < 16; blk++) {
        const int row0 = wrow0 + blk * 8;

        #pragma unroll
        for (int k = 0; k < 8; k++)
            reinterpret_cast<float4*>(xs + k * DDIM)[lane] =
                reinterpret_cast<const float4*>(
                    X + ((size_t)b * LSEQ + row0 + k) * DDIM)[lane];
        __syncwarp();

        u64 aL[8], aH[8];
        #pragma unroll
        for (int k = 0; k < 8; k++) { aL[k] = 0ull; aH[k] = 0ull; }

        #pragma unroll 4
        for (int q = 0; q < DDIM / 4; q++) {
            const ulonglong2 wv = w2[q];
            #pragma unroll
            for (int k = 0; k < 8; k++) {
                const ulonglong2 xv = xs2[k * (DDIM / 4) + q];
                fma2(aL[k], xv.x, wv.x);   // k%4 == 0,1 partials
                fma2(aH[k], xv.y, wv.y);   // k%4 == 2,3 partials
            }
        }
        if (lane < KLAB) {
            #pragma unroll
            for (int k = 0; k < 8; k++) {
                const float e = (lo_f(aL[k]) + hi_f(aL[k]))
                              + (lo_f(aH[k]) + hi_f(aH[k]));
                e_buf[((size_t)b * LSEQ + row0 + k) * EPITCH + lane] = e;
            }
        }
        __syncwarp();
    }
}

// ============================ Kernel B: scan ============================
// 32-row smem ring; 16-row batches prefetched 16 steps ahead:
//   init: rows 0..31 -> ring; LDG rows 32..47 -> regs (pend).
//   at t % 16 == 0 (t >= 16): STS pend (rows t+16..t+31) -> ring half,
//   then LDG rows t+32..t+47 -> pend (coalesced 112 float4, MLP=4).
__global__ __launch_bounds__(64) void crf_scan_kernel(
    const float* __restrict__ T,
    float* __restrict__ out,
    int word0)
{
    __shared__ unsigned char bp_sm[WPB][(LSEQ - 1) * KLAB]; // 2 x 13286 B
    __shared__ __align__(16) float ring_sm[WPB][32 * EPITCH]; // 2 x 3584 B
    __shared__ __align__(16) float l_sm[WPB][32];
    __shared__ unsigned char lab[WPB][LSEQ];

    const int warp = threadIdx.x >> 5;
    const int lane = threadIdx.x & 31;
    const int word = word0 + blockIdx.x * WPB + warp;
    const int yy   = lane < KLAB ? lane : 0;

    F2 T2[13];
    #pragma unroll
    for (int h = 0; h < 13; h++) {
        T2[h].f.x = T[(2 * h)     * KLAB + yy];
        T2[h].f.y = T[(2 * h + 1) * KLAB + yy];
    }

    l_sm[warp][lane] = 0.0f;

    const float* erow = e_buf + (size_t)word * LSEQ * EPITCH;
    const float4* eg4 = reinterpret_cast<const float4*>(erow);
    float* ring = ring_sm[warp];
    float4* ring4 = reinterpret_cast<float4*>(ring);

    // Init: rows 0..31 (= 224 float4, 7 per lane), coalesced.
    #pragma unroll
    for (int u = 0; u < 7; u++)
        ring4[lane + 32 * u] = eg4[lane + 32 * u];

    // Pending batch: rows 32..47 (112 float4 starting at f4 index 224).
    float4 pend[4];
    #pragma unroll
    for (int u = 0; u < 4; u++) {
        const int idx = lane + 32 * u;
        pend[u] = (idx < 112) ? eg4[224 + idx]
                              : make_float4(0.f, 0.f, 0.f, 0.f);
    }
    __syncwarp();

    const ulonglong2* lr2 = reinterpret_cast<const ulonglong2*>(l_sm[warp]);

    float lcur = 0.0f;
    for (int t = 0; t < LSEQ - 1; t++) {
        if ((t & 15) == 0 && t >= 16) {
            // Commit pend (rows t+16..t+31) into its ring half.
            if (t + 16 < LSEQ) {
                float4* dst = ring4 + (((t + 16) & 31) >> 4) * 112 * 0
                            + (((t + 16) & 16) ? 112 : 0);
                #pragma unroll
                for (int u = 0; u < 4; u++) {
                    const int idx = lane + 32 * u;
                    if (idx < 112) dst[idx] = pend[u];
                }
            }
            __syncwarp();
            // Issue next batch: rows t+32..t+47.
            if (t + 32 < LSEQ) {
                const float4* src = eg4 + (size_t)(t + 32) * (EPITCH / 4);
                #pragma unroll
                for (int u = 0; u < 4; u++) {
                    const int idx = lane + 32 * u;
                    if (idx < 112) pend[u] = src[idx];
                }
            }
        }

        const ulonglong2* er2 = reinterpret_cast<const ulonglong2*>(
            ring + (t & 31) * EPITCH);

        // s_j = (e_j + T_jy) + l_j, packed pairs (exact association).
        F2 sv[13];
        #pragma unroll
        for (int h4 = 0; h4 < 7; h4++) {
            const ulonglong2 e4 = er2[h4];
            const ulonglong2 l4 = lr2[h4];
            F2 ea, la, u;
            ea.u = e4.x; la.u = l4.x;
            u = add2(ea, T2[2 * h4]);
            sv[2 * h4] = add2(u, la);
            if (2 * h4 + 1 < 13) {
                F2 ob, lb;
                ob.u = e4.y; lb.u = l4.y;
                u = add2(ob, T2[2 * h4 + 1]);
                sv[2 * h4 + 1] = add2(u, lb);
            }
        }

        // Exact max via fmaxf tree (max is associative).
        float t13[13];
        #pragma unroll
        for (int h = 0; h < 13; h++) t13[h] = fmaxf(sv[h].f.x, sv[h].f.y);
        float r7[7];
        #pragma unroll
        for (int h = 0; h < 6; h++) r7[h] = fmaxf(t13[2 * h], t13[2 * h + 1]);
        r7[6] = t13[12];
        float r4[4];
        r4[0] = fmaxf(r7[0], r7[1]);
        r4[1] = fmaxf(r7[2], r7[3]);
        r4[2] = fmaxf(r7[4], r7[5]);
        r4[3] = r7[6];
        const float m = fmaxf(fmaxf(r4[0], r4[1]), fmaxf(r4[2], r4[3]));

        // First-occurrence argmax: descending eq-chain.
        int am = 25;
        #pragma unroll
        for (int j = 24; j >= 0; j--) {
            const float sj = (j & 1) ? sv[j >> 1].f.y : sv[j >> 1].f.x;
            if (sj == m) am = j;
        }

        if (lane < KLAB) {
            bp_sm[warp][t * KLAB + lane] = (unsigned char)am;
            l_sm[warp][lane] = m;
        }
        lcur = m;
        __syncwarp();
    }

    // Final scores (row 511 read directly from gmem) + warp argmax.
    float fs = (lane < KLAB)
                   ? (erow[(size_t)(LSEQ - 1) * EPITCH + yy] + lcur)
                   : -CUDART_INF_F;
    int idx = lane;
    #pragma unroll
    for (int off = 16; off > 0; off >>= 1) {
        float ov = __shfl_down_sync(0xffffffffu, fs, off);
        int   oi = __shfl_down_sync(0xffffffffu, idx, off);
        if (ov > fs || (ov == fs && oi < idx)) { fs = ov; idx = oi; }
    }
    int y_last = __shfl_sync(0xffffffffu, idx, 0);

    if (lane == 0) {
        int yv = y_last;
        lab[warp][LSEQ - 1] = (unsigned char)yv;
        for (int t = LSEQ - 2; t >= 0; t--) {
            yv = bp_sm[warp][t * KLAB + yv];
            lab[warp][t] = (unsigned char)yv;
        }
    }
    __syncwarp();

    float* orow = out + (size_t)word * LSEQ;
    for (int i = lane; i < LSEQ; i += 32)
        orow[i] = (float)lab[warp][i];
}

extern "C" void kernel_launch(void* const* d_in, const int* in_sizes, int n_in,
                              void* d_out, int out_size)
{
    int ix = 0, it = 0;
    for (int i = 1; i < n_in && i < 3; i++) {
        if (in_sizes[i] > in_sizes[ix]) ix = i;
        if (in_sizes[i] < in_sizes[it]) it = i;
    }
    int iw = 3 - ix - it;
    if (n_in < 3 || iw < 0 || iw > 2 || ix == it) { ix = 0; iw = 1; it = 2; }

    const float* X = (const float*)d_in[ix];
    const float* W = (const float*)d_in[iw];
    const float* T = (const float*)d_in[it];
    float* out = (float*)d_out;
    (void)out_size;

    // Two-stream fork-join pipeline (graph-capture-legal): scan(g) on s1
    // after emit(g); scan(0) overlaps emit(1).
    cudaStream_t s1;
    cudaStreamCreateWithFlags(&s1, cudaStreamNonBlocking);
    cudaEvent_t evFork, evJoin, evE[NGRP];
    cudaEventCreateWithFlags(&evFork, cudaEventDisableTiming);
    cudaEventCreateWithFlags(&evJoin, cudaEventDisableTiming);
    for (int g = 0; g < NGRP; g++)
        cudaEventCreateWithFlags(&evE[g], cudaEventDisableTiming);

    cudaEventRecord(evFork, 0);
    cudaStreamWaitEvent(s1, evFork, 0);

    for (int g = 0; g < NGRP; g++) {
        const int w0 = g * GRPW;
        crf_emit_kernel<<<GRPW, 128, 0, 0>>>(X, W, w0);
        cudaEventRecord(evE[g], 0);
        cudaStreamWaitEvent(s1, evE[g], 0);
        crf_scan_kernel<<<GRPW / WPB, 32 * WPB, 0, s1>>>(T, out, w0);
    }

    cudaEventRecord(evJoin, s1);
    cudaStreamWaitEvent(0, evJoin, 0);
}